// round 15
// baseline (speedup 1.0000x reference)
#include <cuda_runtime.h>
#include <math.h>

typedef unsigned long long ull;

#define BB 128
#define TT 512
#define IND 64
#define HD 256
#define G3 768
#define LD 32
#define NPARD 1056
#define ODD 8

#define CL 4            // cluster size (M split of gate rows / h ownership)
#define NBAT 4          // batches per cluster

// Scratch (static device arrays — no allocation allowed)
__device__ float g_gx[BB*TT*G3];    // 192 MB
__device__ float g_rnn[BB*TT*HD];   // 64 MB

__device__ __forceinline__ float sigm(float x){ return 1.0f/(1.0f+expf(-x)); }

// packed fp32 ops (Blackwell f32x2)
__device__ __forceinline__ ull fma2(ull a, ull b, ull c){
    ull d;
    asm("fma.rn.f32x2 %0, %1, %2, %3;" : "=l"(d) : "l"(a), "l"(b), "l"(c));
    return d;
}
__device__ __forceinline__ ull add2(ull a, ull b){
    ull d;
    asm("add.rn.f32x2 %0, %1, %2;" : "=l"(d) : "l"(a), "l"(b));
    return d;
}
__device__ __forceinline__ float hadd2(ull a){
    unsigned lo, hi;
    asm("mov.b64 {%0,%1}, %2;" : "=r"(lo), "=r"(hi) : "l"(a));
    return __uint_as_float(lo) + __uint_as_float(hi);
}
__device__ __forceinline__ ull pack2(float a, float b){
    return ((ull)__float_as_uint(b) << 32) | (ull)__float_as_uint(a);
}

// ------------------------------------------------------------------
// K1: gx[bt,g] = x[bt,:] . w_ih[g,:] + b_ih[g]   (f32x2 microkernel)
// ------------------------------------------------------------------
__global__ __launch_bounds__(256) void k_gx(const float* __restrict__ x,
                                            const float* __restrict__ w_ih,
                                            const float* __restrict__ b_ih)
{
    __shared__ float2 xs[64][33];
    __shared__ float2 ws[64][33];
    int m0 = blockIdx.y * 64;
    int n0 = blockIdx.x * 64;
    int tid = threadIdx.y * 16 + threadIdx.x;
    const float4* x4 = (const float4*)x;
    const float4* w4 = (const float4*)w_ih;
    for (int q = tid; q < 1024; q += 256) {
        int row = q >> 4, c4 = q & 15;
        float4 v = x4[(size_t)(m0 + row) * 16 + c4];
        xs[row][c4*2+0] = make_float2(v.x, v.y);
        xs[row][c4*2+1] = make_float2(v.z, v.w);
        float4 wv = w4[(size_t)(n0 + row) * 16 + c4];
        ws[row][c4*2+0] = make_float2(wv.x, wv.y);
        ws[row][c4*2+1] = make_float2(wv.z, wv.w);
    }
    __syncthreads();
    int tr = threadIdx.y * 4, tc = threadIdx.x * 4;
    ull acc[4][4] = {};
    #pragma unroll 8
    for (int k2 = 0; k2 < 32; k2++) {
        ull av[4], bv[4];
        #pragma unroll
        for (int i = 0; i < 4; i++) av[i] = *(const ull*)&xs[tr + i][k2];
        #pragma unroll
        for (int j = 0; j < 4; j++) bv[j] = *(const ull*)&ws[tc + j][k2];
        #pragma unroll
        for (int i = 0; i < 4; i++)
            #pragma unroll
            for (int j = 0; j < 4; j++)
                acc[i][j] = fma2(av[i], bv[j], acc[i][j]);
    }
    float b0 = b_ih[n0+tc+0], b1 = b_ih[n0+tc+1], b2 = b_ih[n0+tc+2], b3 = b_ih[n0+tc+3];
    #pragma unroll
    for (int i = 0; i < 4; i++) {
        float4 o;
        o.x = hadd2(acc[i][0]) + b0; o.y = hadd2(acc[i][1]) + b1;
        o.z = hadd2(acc[i][2]) + b2; o.w = hadd2(acc[i][3]) + b3;
        *(float4*)&g_gx[(size_t)(m0 + tr + i) * G3 + n0 + tc] = o;
    }
}

// ------------------------------------------------------------------
// K2: GRU recurrence, M-SPLIT cluster of 4 CTAs.
// CTA rank owns gate rows {r,z,n} for hidden idx [64r, 64r+64):
// 192 rows x K=256. Thread = (row_local, ksec): w = 64 regs,
// partials reduced in LOCAL smem; gates complete locally; only h_new
// (256 floats x 3 remotes) crosses the cluster. h double-buffered,
// one cluster barrier per step.
// ------------------------------------------------------------------
__global__ __launch_bounds__(G3, 1) __cluster_dims__(CL, 1, 1)
void k_gru(const float* __restrict__ hidden,
           const float* __restrict__ w_hh,
           const float* __restrict__ b_hh,
           float* __restrict__ hT)
{
    __shared__ float4 hbuf4[2][NBAT][HD/4];   // full h per batch, double-buffered
    __shared__ float ppart[192][18];          // [row_local][ksec*4 + batch], pad->18
    float* hf = (float*)hbuf4;
    int tid = threadIdx.x;
    unsigned rank;
    asm("mov.u32 %0, %%cluster_ctarank;" : "=r"(rank));
    int b0 = (blockIdx.x / CL) * NBAT;

    // thread -> (row_local 0..191, ksec 0..3)
    int row_local = tid >> 2;
    int ksec = tid & 3;
    int gsec = row_local >> 6;                // 0=r,1=z,2=n
    int jj   = row_local & 63;
    int grow = gsec * HD + 64 * (int)rank + jj;   // global w_hh row

    // w: 64 floats of row grow, K section [64*ksec, 64*ksec+64)
    float4 w[16];
    {
        const float4* wsrc = (const float4*)(w_hh + (size_t)grow * HD + 64 * ksec);
        #pragma unroll
        for (int i = 0; i < 16; i++) w[i] = wsrc[i];
    }

    // gate-thread coords (tid < 256): batch gb, local hidden idx gj
    int gb = tid >> 6, gj = tid & 63;
    int hidx = 64 * (int)rank + gj;
    float bh_r = 0.f, bh_z = 0.f, bh_n = 0.f;
    unsigned hra[3];                          // remote h slots (buf0) in 3 peer CTAs
    if (tid < NBAT * 64) {
        bh_r = b_hh[hidx]; bh_z = b_hh[HD + hidx]; bh_n = b_hh[2*HD + hidx];
        unsigned la = (unsigned)__cvta_generic_to_shared(&hf[gb * HD + hidx]);
        #pragma unroll
        for (int d = 0; d < 3; d++) {
            unsigned dest = (rank + 1 + d) & 3;
            asm("mapa.shared::cluster.u32 %0, %1, %2;" : "=r"(hra[d]) : "r"(la), "r"(dest));
        }
    }
    // init: every CTA loads the FULL h (256) for its 4 batches into buf 0
    for (int q = tid; q < NBAT * HD; q += G3) {
        int b = q >> 8, j = q & 255;
        hf[b * HD + j] = hidden[(size_t)(b0 + b) * HD + j];
    }
    __syncthreads();

    const unsigned HBUF_STRIDE = NBAT * HD * 4;   // bytes between buf0 and buf1

    for (int t = 0; t < TT; t++) {
        int buf = t & 1, nbuf = buf ^ 1;
        // prefetch gx for gate phase
        float xr = 0.f, xz = 0.f, xn = 0.f;
        if (tid < NBAT * 64) {
            const float* gxp = g_gx + ((size_t)(b0 + gb) * TT + t) * G3;
            xr = gxp[hidx]; xz = gxp[HD + hidx]; xn = gxp[2*HD + hidx];
        }
        // row phase: partial over K section for 4 batches (f32x2)
        ull a0 = 0ull, a1 = 0ull, a2 = 0ull, a3 = 0ull;
        #pragma unroll
        for (int k = 0; k < 16; k++) {
            float4 wv = w[k];
            ull w01 = *(const ull*)&wv.x;
            ull w23 = *(const ull*)&wv.z;
            float4 h0 = hbuf4[buf][0][ksec * 16 + k];
            a0 = fma2(w01, *(const ull*)&h0.x, a0);
            a0 = fma2(w23, *(const ull*)&h0.z, a0);
            float4 h1 = hbuf4[buf][1][ksec * 16 + k];
            a1 = fma2(w01, *(const ull*)&h1.x, a1);
            a1 = fma2(w23, *(const ull*)&h1.z, a1);
            float4 h2 = hbuf4[buf][2][ksec * 16 + k];
            a2 = fma2(w01, *(const ull*)&h2.x, a2);
            a2 = fma2(w23, *(const ull*)&h2.z, a2);
            float4 h3 = hbuf4[buf][3][ksec * 16 + k];
            a3 = fma2(w01, *(const ull*)&h3.x, a3);
            a3 = fma2(w23, *(const ull*)&h3.z, a3);
        }
        // local partial store (2x STS.64, 8B-aligned: 72*row + 16*ksec)
        *(ull*)&ppart[row_local][ksec * 4]     = pack2(hadd2(a0), hadd2(a1));
        *(ull*)&ppart[row_local][ksec * 4 + 2] = pack2(hadd2(a2), hadd2(a3));
        __syncthreads();

        // gate phase: fully local reduce + update; broadcast h_new
        if (tid < NBAT * 64) {
            float hr = ppart[gj][gb]       + ppart[gj][4+gb]
                     + ppart[gj][8+gb]     + ppart[gj][12+gb]     + bh_r;
            float hz = ppart[64+gj][gb]    + ppart[64+gj][4+gb]
                     + ppart[64+gj][8+gb]  + ppart[64+gj][12+gb]  + bh_z;
            float hn = ppart[128+gj][gb]   + ppart[128+gj][4+gb]
                     + ppart[128+gj][8+gb] + ppart[128+gj][12+gb] + bh_n;
            float r = sigm(xr + hr);
            float z = sigm(xz + hz);
            float n = tanhf(xn + r * hn);
            float hp = hf[(buf * NBAT + gb) * HD + hidx];
            float hnew = (1.0f - z) * n + z * hp;
            hf[(nbuf * NBAT + gb) * HD + hidx] = hnew;
            unsigned off = (unsigned)nbuf * HBUF_STRIDE;
            asm volatile("st.shared::cluster.f32 [%0], %1;" :: "r"(hra[0] + off), "f"(hnew));
            asm volatile("st.shared::cluster.f32 [%0], %1;" :: "r"(hra[1] + off), "f"(hnew));
            asm volatile("st.shared::cluster.f32 [%0], %1;" :: "r"(hra[2] + off), "f"(hnew));
            g_rnn[((size_t)(b0 + gb) * TT + t) * HD + hidx] = hnew;
        }
        asm volatile("barrier.cluster.arrive.aligned;" ::: "memory");
        asm volatile("barrier.cluster.wait.aligned;"   ::: "memory");
    }
    if (tid < NBAT * 64) hT[(size_t)(b0 + gb) * HD + hidx] = hf[gb * HD + hidx];
}

// ------------------------------------------------------------------
// K3: fused tail — te GEMM + microtiled params GEMM + hyper-MLP.
// (R14 version, unchanged)
// ------------------------------------------------------------------
#define PAIRS 32
#define WT_PITCH 526
#define SM_TE    (PAIRS * 32 * 8)
#define SM_WT    (32 * WT_PITCH * 4)
#define SM_PS    (PAIRS * NPARD * 4)
#define SM_ST    (PAIRS * 48 * 4)
#define SM_HID   (PAIRS * 16 * 4)
#define TAIL_SMEM (SM_TE + SM_WT + SM_PS + SM_ST + SM_HID)

__global__ __launch_bounds__(1024, 1) void k_tail(const float* __restrict__ x,
                                                  const float* __restrict__ w_lat,
                                                  const float* __restrict__ b_lat,
                                                  const float* __restrict__ w_par,
                                                  const float* __restrict__ b_par,
                                                  float* __restrict__ out_mean,
                                                  float* __restrict__ out_std)
{
    extern __shared__ char smem[];
    ull*   te2 = (ull*)smem;
    float* wt  = (float*)(smem + SM_TE);
    float* ps  = (float*)(smem + SM_TE + SM_WT);
    float* st_s= (float*)(smem + SM_TE + SM_WT + SM_PS);
    float* hid = st_s + PAIRS * 48;

    int tid = threadIdx.x;
    int bt0 = blockIdx.x * PAIRS;

    ull* rn2 = (ull*)wt;
    ull* wlt = (ull*)((char*)wt + PAIRS * 128 * 8);
    #pragma unroll
    for (int rep = 0; rep < 2; rep++) {
        int q = tid + rep * 1024;
        {
            int p = q >> 6, c4 = q & 63;
            float4 v = ((const float4*)g_rnn)[((size_t)(bt0 + p) * 64) + c4];
            rn2[p * 128 + c4*2]     = pack2(v.x, v.y);
            rn2[p * 128 + c4*2 + 1] = pack2(v.z, v.w);
        }
        {
            int l = q >> 6, k4 = q & 63;
            float4 v = ((const float4*)w_lat)[(size_t)l * 64 + k4];
            wlt[(2*k4)   * 33 + l] = pack2(v.x, v.y);
            wlt[(2*k4+1) * 33 + l] = pack2(v.z, v.w);
        }
    }
    if (tid < PAIRS * 12) {
        int p = tid / 12, c = tid % 12;
        ((float4*)&st_s[p * 48])[c] = ((const float4*)x)[(size_t)(bt0 + p) * 16 + c];
    }
    __syncthreads();

    {
        int p = tid >> 5, l = tid & 31;
        ull acc = 0ull;
        #pragma unroll 8
        for (int k2 = 0; k2 < 128; k2++)
            acc = fma2(rn2[p * 128 + k2], wlt[k2 * 33 + l], acc);
        float v = hadd2(acc) + b_lat[l];
        unsigned u = __float_as_uint(v);
        te2[p * 32 + l] = ((ull)u << 32) | u;
    }

    int pt    = tid & 127;
    int btile = tid >> 7;
    const ull* myte = &te2[(btile * 4) * 32];

    #pragma unroll 1
    for (int pass = 0; pass < 2; pass++) {
        int idx0 = pass * 512;
        __syncthreads();
        #pragma unroll 1
        for (int q = tid; q < 512 * 8; q += 1024) {
            int i = q >> 3, c4 = q & 7;
            float4 v = ((const float4*)w_par)[(size_t)(idx0 + i) * 8 + c4];
            wt[(c4*4+0) * WT_PITCH + i] = v.x;
            wt[(c4*4+1) * WT_PITCH + i] = v.y;
            wt[(c4*4+2) * WT_PITCH + i] = v.z;
            wt[(c4*4+3) * WT_PITCH + i] = v.w;
        }
        __syncthreads();

        ull acc0[4] = {}, acc1[4] = {};
        #pragma unroll
        for (int k = 0; k < 32; k++) {
            ull wa = *(const ull*)&wt[k * WT_PITCH + 2 * pt];
            ull wb = *(const ull*)&wt[k * WT_PITCH + 2 * pt + 256];
            #pragma unroll
            for (int b = 0; b < 4; b++) {
                ull tv = myte[b * 32 + k];
                acc0[b] = fma2(wa, tv, acc0[b]);
                acc1[b] = fma2(wb, tv, acc1[b]);
            }
        }
        int idxA = idx0 + 2 * pt;
        int idxB = idx0 + 2 * pt + 256;
        ull bbA = *(const ull*)&b_par[idxA];
        ull bbB = *(const ull*)&b_par[idxB];
        #pragma unroll
        for (int b = 0; b < 4; b++) {
            int bt = btile * 4 + b;
            *(ull*)&ps[bt * NPARD + idxA] = add2(acc0[b], bbA);
            *(ull*)&ps[bt * NPARD + idxB] = add2(acc1[b], bbB);
        }
    }

    __syncthreads();
    #pragma unroll 1
    for (int q = tid; q < 32 * 8; q += 1024) {
        int i = q >> 3, c4 = q & 7;
        float4 v = ((const float4*)w_par)[(size_t)(1024 + i) * 8 + c4];
        wt[(c4*4+0) * WT_PITCH + i] = v.x;
        wt[(c4*4+1) * WT_PITCH + i] = v.y;
        wt[(c4*4+2) * WT_PITCH + i] = v.z;
        wt[(c4*4+3) * WT_PITCH + i] = v.w;
    }
    __syncthreads();
    if (tid < 512) {
        int p2 = tid & 15;
        int bt = tid >> 4;
        const ull* bte = &te2[bt * 32];
        ull acc = 0ull;
        #pragma unroll
        for (int k = 0; k < 32; k++)
            acc = fma2(*(const ull*)&wt[k * WT_PITCH + 2 * p2], bte[k], acc);
        int idx = 1024 + 2 * p2;
        ull bb = *(const ull*)&b_par[idx];
        *(ull*)&ps[bt * NPARD + idx] = add2(acc, bb);
    }
    __syncthreads();

    if (tid < PAIRS * 16) {
        int pair = tid >> 4, p = tid & 15;
        const float4* wh4 = (const float4*)(ps + pair * NPARD + p * 48);
        const float4* st4 = (const float4*)&st_s[pair * 48];
        float a = ps[pair * NPARD + 768 + p];
        #pragma unroll
        for (int q = 0; q < 12; q++) {
            float4 wv = wh4[q];
            float4 sv = st4[q];
            a = fmaf(wv.x, sv.x, a); a = fmaf(wv.y, sv.y, a);
            a = fmaf(wv.z, sv.z, a); a = fmaf(wv.w, sv.w, a);
        }
        hid[pair * 16 + p] = tanhf(a);
    }
    __syncthreads();

    if (tid < PAIRS * 16) {
        int pair = tid >> 4, o = tid & 15;
        const float4* wo4 = (const float4*)(ps + pair * NPARD + 784 + o * 16);
        const float4* hv4 = (const float4*)&hid[pair * 16];
        float m = ps[pair * NPARD + 1040 + o];
        #pragma unroll
        for (int q = 0; q < 4; q++) {
            float4 wv = wo4[q];
            float4 hv = hv4[q];
            m = fmaf(wv.x, hv.x, m); m = fmaf(wv.y, hv.y, m);
            m = fmaf(wv.z, hv.z, m); m = fmaf(wv.w, hv.w, m);
        }
        size_t bt = bt0 + pair;
        if (o < 8) out_mean[bt * ODD + o] = m;
        else       out_std[bt * ODD + (o - 8)] = expf(m);
    }
}

// ------------------------------------------------------------------
extern "C" void kernel_launch(void* const* d_in, const int* in_sizes, int n_in,
                              void* d_out, int out_size)
{
    const float* x      = (const float*)d_in[0];
    const float* hidden = (const float*)d_in[1];
    const float* w_ih   = (const float*)d_in[2];
    const float* w_hh   = (const float*)d_in[3];
    const float* b_ih   = (const float*)d_in[4];
    const float* b_hh   = (const float*)d_in[5];
    const float* w_lat  = (const float*)d_in[6];
    const float* b_lat  = (const float*)d_in[7];
    const float* w_par  = (const float*)d_in[8];
    const float* b_par  = (const float*)d_in[9];
    (void)in_sizes; (void)n_in; (void)out_size;

    float* out      = (float*)d_out;
    float* out_mean = out;                                  // B*T*8
    float* out_std  = out + (size_t)BB * TT * ODD;          // B*T*8
    float* out_hT   = out + (size_t)2 * BB * TT * ODD;      // B*256

    cudaFuncSetAttribute(k_tail, cudaFuncAttributeMaxDynamicSharedMemorySize, TAIL_SMEM);

    dim3 g1(G3 / 64, (BB * TT) / 64), b1(16, 16);
    k_gx  <<<g1, b1>>>(x, w_ih, b_ih);
    k_gru <<<(BB / NBAT) * CL, G3>>>(hidden, w_hh, b_hh, out_hT);
    k_tail<<<(BB * TT) / PAIRS, 1024, TAIL_SMEM>>>(x, w_lat, b_lat, w_par, b_par, out_mean, out_std);
}

// round 16
// speedup vs baseline: 3.0195x; 3.0195x over previous
#include <cuda_runtime.h>
#include <math.h>

typedef unsigned long long ull;

#define BB 128
#define TT 512
#define IND 64
#define HD 256
#define G3 768
#define LD 32
#define NPARD 1056
#define ODD 8

#define CL 4            // cluster size (K split of hidden dim)
#define NBAT 4          // batches per cluster
#define KS (HD/CL)      // 64 K-columns per CTA

// Scratch (static device arrays — no allocation allowed)
__device__ float g_gx[BB*TT*G3];    // 192 MB
__device__ float g_rnn[BB*TT*HD];   // 64 MB

// fast gate math: MUFU-based (accuracy budget: rel_err 3e-7 << 1e-3)
__device__ __forceinline__ float sigmf_(float x){
    return __fdividef(1.0f, 1.0f + __expf(-x));
}
__device__ __forceinline__ float tanhf_(float x){
    float e = __expf(-2.0f * x);
    return __fdividef(1.0f - e, 1.0f + e);
}

// packed fp32 ops (Blackwell f32x2)
__device__ __forceinline__ ull fma2(ull a, ull b, ull c){
    ull d;
    asm("fma.rn.f32x2 %0, %1, %2, %3;" : "=l"(d) : "l"(a), "l"(b), "l"(c));
    return d;
}
__device__ __forceinline__ ull add2(ull a, ull b){
    ull d;
    asm("add.rn.f32x2 %0, %1, %2;" : "=l"(d) : "l"(a), "l"(b));
    return d;
}
__device__ __forceinline__ float hadd2(ull a){
    unsigned lo, hi;
    asm("mov.b64 {%0,%1}, %2;" : "=r"(lo), "=r"(hi) : "l"(a));
    return __uint_as_float(lo) + __uint_as_float(hi);
}
__device__ __forceinline__ ull pack2(float a, float b){
    return ((ull)__float_as_uint(b) << 32) | (ull)__float_as_uint(a);
}

// ------------------------------------------------------------------
// K1: gx[bt,g] = x[bt,:] . w_ih[g,:] + b_ih[g]   (f32x2 microkernel)
// ------------------------------------------------------------------
__global__ __launch_bounds__(256) void k_gx(const float* __restrict__ x,
                                            const float* __restrict__ w_ih,
                                            const float* __restrict__ b_ih)
{
    __shared__ float2 xs[64][33];
    __shared__ float2 ws[64][33];
    int m0 = blockIdx.y * 64;
    int n0 = blockIdx.x * 64;
    int tid = threadIdx.y * 16 + threadIdx.x;
    const float4* x4 = (const float4*)x;
    const float4* w4 = (const float4*)w_ih;
    for (int q = tid; q < 1024; q += 256) {
        int row = q >> 4, c4 = q & 15;
        float4 v = x4[(size_t)(m0 + row) * 16 + c4];
        xs[row][c4*2+0] = make_float2(v.x, v.y);
        xs[row][c4*2+1] = make_float2(v.z, v.w);
        float4 wv = w4[(size_t)(n0 + row) * 16 + c4];
        ws[row][c4*2+0] = make_float2(wv.x, wv.y);
        ws[row][c4*2+1] = make_float2(wv.z, wv.w);
    }
    __syncthreads();
    int tr = threadIdx.y * 4, tc = threadIdx.x * 4;
    ull acc[4][4] = {};
    #pragma unroll 8
    for (int k2 = 0; k2 < 32; k2++) {
        ull av[4], bv[4];
        #pragma unroll
        for (int i = 0; i < 4; i++) av[i] = *(const ull*)&xs[tr + i][k2];
        #pragma unroll
        for (int j = 0; j < 4; j++) bv[j] = *(const ull*)&ws[tc + j][k2];
        #pragma unroll
        for (int i = 0; i < 4; i++)
            #pragma unroll
            for (int j = 0; j < 4; j++)
                acc[i][j] = fma2(av[i], bv[j], acc[i][j]);
    }
    float b0 = b_ih[n0+tc+0], b1 = b_ih[n0+tc+1], b2 = b_ih[n0+tc+2], b3 = b_ih[n0+tc+3];
    #pragma unroll
    for (int i = 0; i < 4; i++) {
        float4 o;
        o.x = hadd2(acc[i][0]) + b0; o.y = hadd2(acc[i][1]) + b1;
        o.z = hadd2(acc[i][2]) + b2; o.w = hadd2(acc[i][3]) + b3;
        *(float4*)&g_gx[(size_t)(m0 + tr + i) * G3 + n0 + tc] = o;
    }
}

// ------------------------------------------------------------------
// K2: GRU recurrence (R14 structure, proven best): cluster of 4 CTAs,
// w_hh in regs, f32x2 FMA, packed b64 DSMEM exchange.
// New: arrive/wait split — next-step gx LDG and prev-step g_rnn STG
// issue inside the barrier-wait window; fast gate math.
// ------------------------------------------------------------------
__global__ __launch_bounds__(G3, 1) __cluster_dims__(CL, 1, 1)
void k_gru(const float* __restrict__ hidden,
           const float* __restrict__ w_hh,
           const float* __restrict__ b_hh,
           float* __restrict__ hT)
{
    __shared__ float4 hs4[NBAT][KS/4];            // local hidden slice, 4 x 64
    __shared__ float pbuf[2][CL][192][6];         // [buf][srcCTA][slot][batch(4)+pad2]
    int tid = threadIdx.x;
    unsigned rank;
    asm("mov.u32 %0, %%cluster_ctarank;" : "=r"(rank));
    int b0 = (blockIdx.x / CL) * NBAT;

    float4 w[KS/4];
    {
        const float4* wsrc = (const float4*)(w_hh + (size_t)tid * HD + KS * rank);
        #pragma unroll
        for (int i = 0; i < KS/4; i++) w[i] = wsrc[i];
    }

    float* hs = (float*)hs4;
    int gb = tid >> 6, gj = tid & 63;
    int hidx = KS * (int)rank + gj;
    bool isgate = (tid < NBAT * KS);
    float bh_r = 0.f, bh_z = 0.f, bh_n = 0.f;
    if (isgate) {
        hs[gb * KS + gj] = hidden[(size_t)(b0 + gb) * HD + hidx];
        bh_r = b_hh[hidx]; bh_z = b_hh[HD + hidx]; bh_n = b_hh[2*HD + hidx];
    }

    // routing: row r=tid -> dest CTA=(r&255)>>6, slot=(r>>8)*64+(r&63)
    int dest = (tid & 255) >> 6;
    int slot = (tid >> 8) * 64 + (tid & 63);
    unsigned raddr0, raddr1;
    {
        unsigned la0 = (unsigned)__cvta_generic_to_shared(&pbuf[0][rank][slot][0]);
        unsigned la1 = (unsigned)__cvta_generic_to_shared(&pbuf[1][rank][slot][0]);
        asm("mapa.shared::cluster.u32 %0, %1, %2;" : "=r"(raddr0) : "r"(la0), "r"(dest));
        asm("mapa.shared::cluster.u32 %0, %1, %2;" : "=r"(raddr1) : "r"(la1), "r"(dest));
    }
    __syncthreads();

    const float* gxp = g_gx + ((size_t)(b0 + gb) * TT) * G3;
    float* rnnp = g_rnn + ((size_t)(b0 + gb) * TT) * HD + hidx;

    // preload gx for t=0
    float xr = 0.f, xz = 0.f, xn = 0.f;
    if (isgate) { xr = gxp[hidx]; xz = gxp[HD + hidx]; xn = gxp[2*HD + hidx]; }
    float hkeep = 0.f;

    for (int t = 0; t < TT; t++) {
        // partial gh for 4 batches over local K slice (f32x2, LDS.128 h)
        ull a0 = 0ull, a1 = 0ull, a2 = 0ull, a3 = 0ull;
        #pragma unroll
        for (int k = 0; k < KS/4; k++) {
            float4 wv = w[k];
            ull w01 = *(const ull*)&wv.x;
            ull w23 = *(const ull*)&wv.z;
            float4 h0 = hs4[0][k];
            a0 = fma2(w01, *(const ull*)&h0.x, a0);
            a0 = fma2(w23, *(const ull*)&h0.z, a0);
            float4 h1 = hs4[1][k];
            a1 = fma2(w01, *(const ull*)&h1.x, a1);
            a1 = fma2(w23, *(const ull*)&h1.z, a1);
            float4 h2 = hs4[2][k];
            a2 = fma2(w01, *(const ull*)&h2.x, a2);
            a2 = fma2(w23, *(const ull*)&h2.z, a2);
            float4 h3 = hs4[3][k];
            a3 = fma2(w01, *(const ull*)&h3.x, a3);
            a3 = fma2(w23, *(const ull*)&h3.z, a3);
        }
        float s0 = hadd2(a0), s1 = hadd2(a1), s2 = hadd2(a2), s3 = hadd2(a3);

        // ship partials: 2 packed b64 DSMEM stores, then arrive
        unsigned ra = (t & 1) ? raddr1 : raddr0;
        ull p01 = pack2(s0, s1);
        ull p23 = pack2(s2, s3);
        asm volatile("st.shared::cluster.b64 [%0], %1;" :: "r"(ra),      "l"(p01));
        asm volatile("st.shared::cluster.b64 [%0], %1;" :: "r"(ra + 8u), "l"(p23));
        asm volatile("barrier.cluster.arrive.aligned;" ::: "memory");

        // barrier-wait window: issue independent global traffic
        float xrn = 0.f, xzn = 0.f, xnn = 0.f;
        if (isgate) {
            if (t + 1 < TT) {
                const float* gx1 = gxp + (size_t)(t + 1) * G3;
                xrn = gx1[hidx]; xzn = gx1[HD + hidx]; xnn = gx1[2*HD + hidx];
            }
            if (t > 0) rnnp[(size_t)(t - 1) * HD] = hkeep;   // deferred store
        }
        asm volatile("barrier.cluster.wait.aligned;" ::: "memory");

        // gate phase
        if (isgate) {
            int buf = t & 1;
            float hr = pbuf[buf][0][gj][gb]      + pbuf[buf][1][gj][gb]
                     + pbuf[buf][2][gj][gb]      + pbuf[buf][3][gj][gb]      + bh_r;
            float hz = pbuf[buf][0][64+gj][gb]   + pbuf[buf][1][64+gj][gb]
                     + pbuf[buf][2][64+gj][gb]   + pbuf[buf][3][64+gj][gb]   + bh_z;
            float hn = pbuf[buf][0][128+gj][gb]  + pbuf[buf][1][128+gj][gb]
                     + pbuf[buf][2][128+gj][gb]  + pbuf[buf][3][128+gj][gb]  + bh_n;
            float r = sigmf_(xr + hr);
            float z = sigmf_(xz + hz);
            float n = tanhf_(xn + r * hn);
            float hp = hs[gb*KS + gj];
            float hnew = (1.0f - z) * n + z * hp;
            hs[gb*KS + gj] = hnew;
            hkeep = hnew;
        }
        xr = xrn; xz = xzn; xn = xnn;
        __syncthreads();
    }
    if (isgate) {
        rnnp[(size_t)(TT - 1) * HD] = hkeep;
        hT[(size_t)(b0 + gb) * HD + hidx] = hkeep;
    }
}

// ------------------------------------------------------------------
// K3: fused tail — te GEMM + microtiled params GEMM + hyper-MLP.
// (R14 version; only expf -> __expf)
// ------------------------------------------------------------------
#define PAIRS 32
#define WT_PITCH 526
#define SM_TE    (PAIRS * 32 * 8)
#define SM_WT    (32 * WT_PITCH * 4)
#define SM_PS    (PAIRS * NPARD * 4)
#define SM_ST    (PAIRS * 48 * 4)
#define SM_HID   (PAIRS * 16 * 4)
#define TAIL_SMEM (SM_TE + SM_WT + SM_PS + SM_ST + SM_HID)

__global__ __launch_bounds__(1024, 1) void k_tail(const float* __restrict__ x,
                                                  const float* __restrict__ w_lat,
                                                  const float* __restrict__ b_lat,
                                                  const float* __restrict__ w_par,
                                                  const float* __restrict__ b_par,
                                                  float* __restrict__ out_mean,
                                                  float* __restrict__ out_std)
{
    extern __shared__ char smem[];
    ull*   te2 = (ull*)smem;
    float* wt  = (float*)(smem + SM_TE);
    float* ps  = (float*)(smem + SM_TE + SM_WT);
    float* st_s= (float*)(smem + SM_TE + SM_WT + SM_PS);
    float* hid = st_s + PAIRS * 48;

    int tid = threadIdx.x;
    int bt0 = blockIdx.x * PAIRS;

    ull* rn2 = (ull*)wt;
    ull* wlt = (ull*)((char*)wt + PAIRS * 128 * 8);
    #pragma unroll
    for (int rep = 0; rep < 2; rep++) {
        int q = tid + rep * 1024;
        {
            int p = q >> 6, c4 = q & 63;
            float4 v = ((const float4*)g_rnn)[((size_t)(bt0 + p) * 64) + c4];
            rn2[p * 128 + c4*2]     = pack2(v.x, v.y);
            rn2[p * 128 + c4*2 + 1] = pack2(v.z, v.w);
        }
        {
            int l = q >> 6, k4 = q & 63;
            float4 v = ((const float4*)w_lat)[(size_t)l * 64 + k4];
            wlt[(2*k4)   * 33 + l] = pack2(v.x, v.y);
            wlt[(2*k4+1) * 33 + l] = pack2(v.z, v.w);
        }
    }
    if (tid < PAIRS * 12) {
        int p = tid / 12, c = tid % 12;
        ((float4*)&st_s[p * 48])[c] = ((const float4*)x)[(size_t)(bt0 + p) * 16 + c];
    }
    __syncthreads();

    {
        int p = tid >> 5, l = tid & 31;
        ull acc = 0ull;
        #pragma unroll 8
        for (int k2 = 0; k2 < 128; k2++)
            acc = fma2(rn2[p * 128 + k2], wlt[k2 * 33 + l], acc);
        float v = hadd2(acc) + b_lat[l];
        unsigned u = __float_as_uint(v);
        te2[p * 32 + l] = ((ull)u << 32) | u;
    }

    int pt    = tid & 127;
    int btile = tid >> 7;
    const ull* myte = &te2[(btile * 4) * 32];

    #pragma unroll 1
    for (int pass = 0; pass < 2; pass++) {
        int idx0 = pass * 512;
        __syncthreads();
        #pragma unroll 1
        for (int q = tid; q < 512 * 8; q += 1024) {
            int i = q >> 3, c4 = q & 7;
            float4 v = ((const float4*)w_par)[(size_t)(idx0 + i) * 8 + c4];
            wt[(c4*4+0) * WT_PITCH + i] = v.x;
            wt[(c4*4+1) * WT_PITCH + i] = v.y;
            wt[(c4*4+2) * WT_PITCH + i] = v.z;
            wt[(c4*4+3) * WT_PITCH + i] = v.w;
        }
        __syncthreads();

        ull acc0[4] = {}, acc1[4] = {};
        #pragma unroll
        for (int k = 0; k < 32; k++) {
            ull wa = *(const ull*)&wt[k * WT_PITCH + 2 * pt];
            ull wb = *(const ull*)&wt[k * WT_PITCH + 2 * pt + 256];
            #pragma unroll
            for (int b = 0; b < 4; b++) {
                ull tv = myte[b * 32 + k];
                acc0[b] = fma2(wa, tv, acc0[b]);
                acc1[b] = fma2(wb, tv, acc1[b]);
            }
        }
        int idxA = idx0 + 2 * pt;
        int idxB = idx0 + 2 * pt + 256;
        ull bbA = *(const ull*)&b_par[idxA];
        ull bbB = *(const ull*)&b_par[idxB];
        #pragma unroll
        for (int b = 0; b < 4; b++) {
            int bt = btile * 4 + b;
            *(ull*)&ps[bt * NPARD + idxA] = add2(acc0[b], bbA);
            *(ull*)&ps[bt * NPARD + idxB] = add2(acc1[b], bbB);
        }
    }

    __syncthreads();
    #pragma unroll 1
    for (int q = tid; q < 32 * 8; q += 1024) {
        int i = q >> 3, c4 = q & 7;
        float4 v = ((const float4*)w_par)[(size_t)(1024 + i) * 8 + c4];
        wt[(c4*4+0) * WT_PITCH + i] = v.x;
        wt[(c4*4+1) * WT_PITCH + i] = v.y;
        wt[(c4*4+2) * WT_PITCH + i] = v.z;
        wt[(c4*4+3) * WT_PITCH + i] = v.w;
    }
    __syncthreads();
    if (tid < 512) {
        int p2 = tid & 15;
        int bt = tid >> 4;
        const ull* bte = &te2[bt * 32];
        ull acc = 0ull;
        #pragma unroll
        for (int k = 0; k < 32; k++)
            acc = fma2(*(const ull*)&wt[k * WT_PITCH + 2 * p2], bte[k], acc);
        int idx = 1024 + 2 * p2;
        ull bb = *(const ull*)&b_par[idx];
        *(ull*)&ps[bt * NPARD + idx] = add2(acc, bb);
    }
    __syncthreads();

    if (tid < PAIRS * 16) {
        int pair = tid >> 4, p = tid & 15;
        const float4* wh4 = (const float4*)(ps + pair * NPARD + p * 48);
        const float4* st4 = (const float4*)&st_s[pair * 48];
        float a = ps[pair * NPARD + 768 + p];
        #pragma unroll
        for (int q = 0; q < 12; q++) {
            float4 wv = wh4[q];
            float4 sv = st4[q];
            a = fmaf(wv.x, sv.x, a); a = fmaf(wv.y, sv.y, a);
            a = fmaf(wv.z, sv.z, a); a = fmaf(wv.w, sv.w, a);
        }
        float e = __expf(-2.0f * a);
        hid[pair * 16 + p] = __fdividef(1.0f - e, 1.0f + e);
    }
    __syncthreads();

    if (tid < PAIRS * 16) {
        int pair = tid >> 4, o = tid & 15;
        const float4* wo4 = (const float4*)(ps + pair * NPARD + 784 + o * 16);
        const float4* hv4 = (const float4*)&hid[pair * 16];
        float m = ps[pair * NPARD + 1040 + o];
        #pragma unroll
        for (int q = 0; q < 4; q++) {
            float4 wv = wo4[q];
            float4 hv = hv4[q];
            m = fmaf(wv.x, hv.x, m); m = fmaf(wv.y, hv.y, m);
            m = fmaf(wv.z, hv.z, m); m = fmaf(wv.w, hv.w, m);
        }
        size_t bt = bt0 + pair;
        if (o < 8) out_mean[bt * ODD + o] = m;
        else       out_std[bt * ODD + (o - 8)] = __expf(m);
    }
}

// ------------------------------------------------------------------
extern "C" void kernel_launch(void* const* d_in, const int* in_sizes, int n_in,
                              void* d_out, int out_size)
{
    const float* x      = (const float*)d_in[0];
    const float* hidden = (const float*)d_in[1];
    const float* w_ih   = (const float*)d_in[2];
    const float* w_hh   = (const float*)d_in[3];
    const float* b_ih   = (const float*)d_in[4];
    const float* b_hh   = (const float*)d_in[5];
    const float* w_lat  = (const float*)d_in[6];
    const float* b_lat  = (const float*)d_in[7];
    const float* w_par  = (const float*)d_in[8];
    const float* b_par  = (const float*)d_in[9];
    (void)in_sizes; (void)n_in; (void)out_size;

    float* out      = (float*)d_out;
    float* out_mean = out;                                  // B*T*8
    float* out_std  = out + (size_t)BB * TT * ODD;          // B*T*8
    float* out_hT   = out + (size_t)2 * BB * TT * ODD;      // B*256

    cudaFuncSetAttribute(k_tail, cudaFuncAttributeMaxDynamicSharedMemorySize, TAIL_SMEM);

    dim3 g1(G3 / 64, (BB * TT) / 64), b1(16, 16);
    k_gx  <<<g1, b1>>>(x, w_ih, b_ih);
    k_gru <<<(BB / NBAT) * CL, G3>>>(hidden, w_hh, b_hh, out_hT);
    k_tail<<<(BB * TT) / PAIRS, 1024, TAIL_SMEM>>>(x, w_lat, b_lat, w_par, b_par, out_mean, out_std);
}

// round 17
// speedup vs baseline: 3.2499x; 1.0763x over previous
#include <cuda_runtime.h>
#include <math.h>

typedef unsigned long long ull;

#define BB 128
#define TT 512
#define IND 64
#define HD 256
#define G3 768
#define LD 32
#define NPARD 1056
#define ODD 8

#define CL 4            // cluster size (K split of hidden dim)
#define NBAT 4          // batches per cluster
#define KS (HD/CL)      // 64 K-columns per CTA

// Scratch (static device arrays — no allocation allowed)
__device__ float g_gx[BB*TT*G3];    // 192 MB
__device__ float g_rnn[BB*TT*HD];   // 64 MB

__device__ __forceinline__ float sigm(float x){ return 1.0f/(1.0f+expf(-x)); }

// packed fp32 ops (Blackwell f32x2)
__device__ __forceinline__ ull fma2(ull a, ull b, ull c){
    ull d;
    asm("fma.rn.f32x2 %0, %1, %2, %3;" : "=l"(d) : "l"(a), "l"(b), "l"(c));
    return d;
}
__device__ __forceinline__ ull add2(ull a, ull b){
    ull d;
    asm("add.rn.f32x2 %0, %1, %2;" : "=l"(d) : "l"(a), "l"(b));
    return d;
}
__device__ __forceinline__ float hadd2(ull a){
    unsigned lo, hi;
    asm("mov.b64 {%0,%1}, %2;" : "=r"(lo), "=r"(hi) : "l"(a));
    return __uint_as_float(lo) + __uint_as_float(hi);
}
__device__ __forceinline__ ull pack2(float a, float b){
    return ((ull)__float_as_uint(b) << 32) | (ull)__float_as_uint(a);
}

// ------------------------------------------------------------------
// K1: gx = x @ w_ih^T + b_ih.  Tile 128(bt) x 64(gate), 8x4 microtile:
// conflicted bv loads amortized over 2x rows => 0.75 phases/fma2.
// ------------------------------------------------------------------
#define GX_SMEM ((128*33 + 64*33) * 8)   // float2 arrays, 50688 B
__global__ __launch_bounds__(256) void k_gx(const float* __restrict__ x,
                                            const float* __restrict__ w_ih,
                                            const float* __restrict__ b_ih)
{
    extern __shared__ float2 sm2[];
    float2* xs = sm2;                 // [128][33]
    float2* ws = sm2 + 128 * 33;      // [64][33]
    int m0 = blockIdx.y * 128;
    int n0 = blockIdx.x * 64;
    int tid = threadIdx.y * 16 + threadIdx.x;
    const float4* x4 = (const float4*)x;
    const float4* w4 = (const float4*)w_ih;
    for (int q = tid; q < 2048; q += 256) {
        int row = q >> 4, c4 = q & 15;
        float4 v = x4[(size_t)(m0 + row) * 16 + c4];
        xs[row*33 + c4*2]     = make_float2(v.x, v.y);
        xs[row*33 + c4*2 + 1] = make_float2(v.z, v.w);
    }
    for (int q = tid; q < 1024; q += 256) {
        int row = q >> 4, c4 = q & 15;
        float4 wv = w4[(size_t)(n0 + row) * 16 + c4];
        ws[row*33 + c4*2]     = make_float2(wv.x, wv.y);
        ws[row*33 + c4*2 + 1] = make_float2(wv.z, wv.w);
    }
    __syncthreads();
    int tr = threadIdx.y * 8, tc = threadIdx.x * 4;
    ull acc[8][4] = {};
    #pragma unroll 4
    for (int k2 = 0; k2 < 32; k2++) {
        ull av[8], bv[4];
        #pragma unroll
        for (int j = 0; j < 4; j++) bv[j] = *(const ull*)&ws[(tc + j)*33 + k2];
        #pragma unroll
        for (int i = 0; i < 8; i++) av[i] = *(const ull*)&xs[(tr + i)*33 + k2];
        #pragma unroll
        for (int i = 0; i < 8; i++)
            #pragma unroll
            for (int j = 0; j < 4; j++)
                acc[i][j] = fma2(av[i], bv[j], acc[i][j]);
    }
    float b0 = b_ih[n0+tc+0], b1 = b_ih[n0+tc+1], b2 = b_ih[n0+tc+2], b3 = b_ih[n0+tc+3];
    #pragma unroll
    for (int i = 0; i < 8; i++) {
        float4 o;
        o.x = hadd2(acc[i][0]) + b0; o.y = hadd2(acc[i][1]) + b1;
        o.z = hadd2(acc[i][2]) + b2; o.w = hadd2(acc[i][3]) + b3;
        *(float4*)&g_gx[(size_t)(m0 + tr + i) * G3 + n0 + tc] = o;
    }
}

// ------------------------------------------------------------------
// K2: GRU recurrence (EXACT R14, proven best): cluster of 4 CTAs,
// w_hh in regs, f32x2 FMA, packed b64 DSMEM exchange, single barrier.
// ------------------------------------------------------------------
__global__ __launch_bounds__(G3, 1) __cluster_dims__(CL, 1, 1)
void k_gru(const float* __restrict__ hidden,
           const float* __restrict__ w_hh,
           const float* __restrict__ b_hh,
           float* __restrict__ hT)
{
    __shared__ float4 hs4[NBAT][KS/4];            // local hidden slice, 4 x 64
    __shared__ float pbuf[2][CL][192][6];         // [buf][srcCTA][slot][batch(4)+pad2]
    int tid = threadIdx.x;
    unsigned rank;
    asm("mov.u32 %0, %%cluster_ctarank;" : "=r"(rank));
    int b0 = (blockIdx.x / CL) * NBAT;

    float4 w[KS/4];
    {
        const float4* wsrc = (const float4*)(w_hh + (size_t)tid * HD + KS * rank);
        #pragma unroll
        for (int i = 0; i < KS/4; i++) w[i] = wsrc[i];
    }

    float* hs = (float*)hs4;
    int gb = tid >> 6, gj = tid & 63;
    int hidx = KS * (int)rank + gj;
    float bh_r = 0.f, bh_z = 0.f, bh_n = 0.f;
    if (tid < NBAT * KS) {
        hs[gb * KS + gj] = hidden[(size_t)(b0 + gb) * HD + hidx];
        bh_r = b_hh[hidx]; bh_z = b_hh[HD + hidx]; bh_n = b_hh[2*HD + hidx];
    }

    // routing: row r=tid -> dest CTA=(r&255)>>6, slot=(r>>8)*64+(r&63)
    int dest = (tid & 255) >> 6;
    int slot = (tid >> 8) * 64 + (tid & 63);
    unsigned raddr0, raddr1;
    {
        unsigned la0 = (unsigned)__cvta_generic_to_shared(&pbuf[0][rank][slot][0]);
        unsigned la1 = (unsigned)__cvta_generic_to_shared(&pbuf[1][rank][slot][0]);
        asm("mapa.shared::cluster.u32 %0, %1, %2;" : "=r"(raddr0) : "r"(la0), "r"(dest));
        asm("mapa.shared::cluster.u32 %0, %1, %2;" : "=r"(raddr1) : "r"(la1), "r"(dest));
    }
    __syncthreads();

    for (int t = 0; t < TT; t++) {
        // prefetch gx (long-scoreboard covered by FMA block below)
        float xr = 0.f, xz = 0.f, xn = 0.f;
        if (tid < NBAT * KS) {
            const float* gxp = g_gx + ((size_t)(b0 + gb) * TT + t) * G3;
            xr = gxp[hidx]; xz = gxp[HD + hidx]; xn = gxp[2*HD + hidx];
        }
        // partial gh for 4 batches over local K slice (f32x2, LDS.128 h)
        ull a0 = 0ull, a1 = 0ull, a2 = 0ull, a3 = 0ull;
        #pragma unroll
        for (int k = 0; k < KS/4; k++) {
            float4 wv = w[k];
            ull w01 = *(const ull*)&wv.x;
            ull w23 = *(const ull*)&wv.z;
            float4 h0 = hs4[0][k];
            a0 = fma2(w01, *(const ull*)&h0.x, a0);
            a0 = fma2(w23, *(const ull*)&h0.z, a0);
            float4 h1 = hs4[1][k];
            a1 = fma2(w01, *(const ull*)&h1.x, a1);
            a1 = fma2(w23, *(const ull*)&h1.z, a1);
            float4 h2 = hs4[2][k];
            a2 = fma2(w01, *(const ull*)&h2.x, a2);
            a2 = fma2(w23, *(const ull*)&h2.z, a2);
            float4 h3 = hs4[3][k];
            a3 = fma2(w01, *(const ull*)&h3.x, a3);
            a3 = fma2(w23, *(const ull*)&h3.z, a3);
        }
        float s0 = hadd2(a0), s1 = hadd2(a1), s2 = hadd2(a2), s3 = hadd2(a3);

        // ship partials to owning CTA: 2 packed b64 DSMEM stores (16B total)
        unsigned ra = (t & 1) ? raddr1 : raddr0;
        ull p01 = pack2(s0, s1);
        ull p23 = pack2(s2, s3);
        asm volatile("st.shared::cluster.b64 [%0], %1;"     :: "r"(ra),      "l"(p01));
        asm volatile("st.shared::cluster.b64 [%0], %1;"     :: "r"(ra + 8u), "l"(p23));
        asm volatile("barrier.cluster.arrive.aligned;" ::: "memory");
        asm volatile("barrier.cluster.wait.aligned;"   ::: "memory");

        // gate phase: combine 4 partials per gate, update local h slice
        if (tid < NBAT * KS) {
            int buf = t & 1;
            float hr = pbuf[buf][0][gj][gb]      + pbuf[buf][1][gj][gb]
                     + pbuf[buf][2][gj][gb]      + pbuf[buf][3][gj][gb]      + bh_r;
            float hz = pbuf[buf][0][64+gj][gb]   + pbuf[buf][1][64+gj][gb]
                     + pbuf[buf][2][64+gj][gb]   + pbuf[buf][3][64+gj][gb]   + bh_z;
            float hn = pbuf[buf][0][128+gj][gb]  + pbuf[buf][1][128+gj][gb]
                     + pbuf[buf][2][128+gj][gb]  + pbuf[buf][3][128+gj][gb]  + bh_n;
            float r = sigm(xr + hr);
            float z = sigm(xz + hz);
            float n = tanhf(xn + r * hn);
            float hp = hs[gb*KS + gj];
            float hnew = (1.0f - z) * n + z * hp;
            hs[gb*KS + gj] = hnew;
            g_rnn[((size_t)(b0 + gb) * TT + t) * HD + hidx] = hnew;
        }
        __syncthreads();
    }
    if (tid < NBAT * KS) hT[(size_t)(b0 + gb) * HD + hidx] = hs[gb*KS + gj];
}

// ------------------------------------------------------------------
// K3: fused tail — te GEMM + microtiled params GEMM + hyper-MLP.
// (R14 structure; __expf fast math in epilogue, validated R16)
// ------------------------------------------------------------------
#define PAIRS 32
#define WT_PITCH 526
#define SM_TE    (PAIRS * 32 * 8)
#define SM_WT    (32 * WT_PITCH * 4)
#define SM_PS    (PAIRS * NPARD * 4)
#define SM_ST    (PAIRS * 48 * 4)
#define SM_HID   (PAIRS * 16 * 4)
#define TAIL_SMEM (SM_TE + SM_WT + SM_PS + SM_ST + SM_HID)

__global__ __launch_bounds__(1024, 1) void k_tail(const float* __restrict__ x,
                                                  const float* __restrict__ w_lat,
                                                  const float* __restrict__ b_lat,
                                                  const float* __restrict__ w_par,
                                                  const float* __restrict__ b_par,
                                                  float* __restrict__ out_mean,
                                                  float* __restrict__ out_std)
{
    extern __shared__ char smem[];
    ull*   te2 = (ull*)smem;
    float* wt  = (float*)(smem + SM_TE);
    float* ps  = (float*)(smem + SM_TE + SM_WT);
    float* st_s= (float*)(smem + SM_TE + SM_WT + SM_PS);
    float* hid = st_s + PAIRS * 48;

    int tid = threadIdx.x;
    int bt0 = blockIdx.x * PAIRS;

    ull* rn2 = (ull*)wt;
    ull* wlt = (ull*)((char*)wt + PAIRS * 128 * 8);
    #pragma unroll
    for (int rep = 0; rep < 2; rep++) {
        int q = tid + rep * 1024;
        {
            int p = q >> 6, c4 = q & 63;
            float4 v = ((const float4*)g_rnn)[((size_t)(bt0 + p) * 64) + c4];
            rn2[p * 128 + c4*2]     = pack2(v.x, v.y);
            rn2[p * 128 + c4*2 + 1] = pack2(v.z, v.w);
        }
        {
            int l = q >> 6, k4 = q & 63;
            float4 v = ((const float4*)w_lat)[(size_t)l * 64 + k4];
            wlt[(2*k4)   * 33 + l] = pack2(v.x, v.y);
            wlt[(2*k4+1) * 33 + l] = pack2(v.z, v.w);
        }
    }
    if (tid < PAIRS * 12) {
        int p = tid / 12, c = tid % 12;
        ((float4*)&st_s[p * 48])[c] = ((const float4*)x)[(size_t)(bt0 + p) * 16 + c];
    }
    __syncthreads();

    {
        int p = tid >> 5, l = tid & 31;
        ull acc = 0ull;
        #pragma unroll 8
        for (int k2 = 0; k2 < 128; k2++)
            acc = fma2(rn2[p * 128 + k2], wlt[k2 * 33 + l], acc);
        float v = hadd2(acc) + b_lat[l];
        unsigned u = __float_as_uint(v);
        te2[p * 32 + l] = ((ull)u << 32) | u;
    }

    int pt    = tid & 127;
    int btile = tid >> 7;
    const ull* myte = &te2[(btile * 4) * 32];

    #pragma unroll 1
    for (int pass = 0; pass < 2; pass++) {
        int idx0 = pass * 512;
        __syncthreads();
        #pragma unroll 1
        for (int q = tid; q < 512 * 8; q += 1024) {
            int i = q >> 3, c4 = q & 7;
            float4 v = ((const float4*)w_par)[(size_t)(idx0 + i) * 8 + c4];
            wt[(c4*4+0) * WT_PITCH + i] = v.x;
            wt[(c4*4+1) * WT_PITCH + i] = v.y;
            wt[(c4*4+2) * WT_PITCH + i] = v.z;
            wt[(c4*4+3) * WT_PITCH + i] = v.w;
        }
        __syncthreads();

        ull acc0[4] = {}, acc1[4] = {};
        #pragma unroll
        for (int k = 0; k < 32; k++) {
            ull wa = *(const ull*)&wt[k * WT_PITCH + 2 * pt];
            ull wb = *(const ull*)&wt[k * WT_PITCH + 2 * pt + 256];
            #pragma unroll
            for (int b = 0; b < 4; b++) {
                ull tv = myte[b * 32 + k];
                acc0[b] = fma2(wa, tv, acc0[b]);
                acc1[b] = fma2(wb, tv, acc1[b]);
            }
        }
        int idxA = idx0 + 2 * pt;
        int idxB = idx0 + 2 * pt + 256;
        ull bbA = *(const ull*)&b_par[idxA];
        ull bbB = *(const ull*)&b_par[idxB];
        #pragma unroll
        for (int b = 0; b < 4; b++) {
            int bt = btile * 4 + b;
            *(ull*)&ps[bt * NPARD + idxA] = add2(acc0[b], bbA);
            *(ull*)&ps[bt * NPARD + idxB] = add2(acc1[b], bbB);
        }
    }

    __syncthreads();
    #pragma unroll 1
    for (int q = tid; q < 32 * 8; q += 1024) {
        int i = q >> 3, c4 = q & 7;
        float4 v = ((const float4*)w_par)[(size_t)(1024 + i) * 8 + c4];
        wt[(c4*4+0) * WT_PITCH + i] = v.x;
        wt[(c4*4+1) * WT_PITCH + i] = v.y;
        wt[(c4*4+2) * WT_PITCH + i] = v.z;
        wt[(c4*4+3) * WT_PITCH + i] = v.w;
    }
    __syncthreads();
    if (tid < 512) {
        int p2 = tid & 15;
        int bt = tid >> 4;
        const ull* bte = &te2[bt * 32];
        ull acc = 0ull;
        #pragma unroll
        for (int k = 0; k < 32; k++)
            acc = fma2(*(const ull*)&wt[k * WT_PITCH + 2 * p2], bte[k], acc);
        int idx = 1024 + 2 * p2;
        ull bb = *(const ull*)&b_par[idx];
        *(ull*)&ps[bt * NPARD + idx] = add2(acc, bb);
    }
    __syncthreads();

    if (tid < PAIRS * 16) {
        int pair = tid >> 4, p = tid & 15;
        const float4* wh4 = (const float4*)(ps + pair * NPARD + p * 48);
        const float4* st4 = (const float4*)&st_s[pair * 48];
        float a = ps[pair * NPARD + 768 + p];
        #pragma unroll
        for (int q = 0; q < 12; q++) {
            float4 wv = wh4[q];
            float4 sv = st4[q];
            a = fmaf(wv.x, sv.x, a); a = fmaf(wv.y, sv.y, a);
            a = fmaf(wv.z, sv.z, a); a = fmaf(wv.w, sv.w, a);
        }
        float e = __expf(-2.0f * a);
        hid[pair * 16 + p] = __fdividef(1.0f - e, 1.0f + e);
    }
    __syncthreads();

    if (tid < PAIRS * 16) {
        int pair = tid >> 4, o = tid & 15;
        const float4* wo4 = (const float4*)(ps + pair * NPARD + 784 + o * 16);
        const float4* hv4 = (const float4*)&hid[pair * 16];
        float m = ps[pair * NPARD + 1040 + o];
        #pragma unroll
        for (int q = 0; q < 4; q++) {
            float4 wv = wo4[q];
            float4 hv = hv4[q];
            m = fmaf(wv.x, hv.x, m); m = fmaf(wv.y, hv.y, m);
            m = fmaf(wv.z, hv.z, m); m = fmaf(wv.w, hv.w, m);
        }
        size_t bt = bt0 + pair;
        if (o < 8) out_mean[bt * ODD + o] = m;
        else       out_std[bt * ODD + (o - 8)] = __expf(m);
    }
}

// ------------------------------------------------------------------
extern "C" void kernel_launch(void* const* d_in, const int* in_sizes, int n_in,
                              void* d_out, int out_size)
{
    const float* x      = (const float*)d_in[0];
    const float* hidden = (const float*)d_in[1];
    const float* w_ih   = (const float*)d_in[2];
    const float* w_hh   = (const float*)d_in[3];
    const float* b_ih   = (const float*)d_in[4];
    const float* b_hh   = (const float*)d_in[5];
    const float* w_lat  = (const float*)d_in[6];
    const float* b_lat  = (const float*)d_in[7];
    const float* w_par  = (const float*)d_in[8];
    const float* b_par  = (const float*)d_in[9];
    (void)in_sizes; (void)n_in; (void)out_size;

    float* out      = (float*)d_out;
    float* out_mean = out;                                  // B*T*8
    float* out_std  = out + (size_t)BB * TT * ODD;          // B*T*8
    float* out_hT   = out + (size_t)2 * BB * TT * ODD;      // B*256

    cudaFuncSetAttribute(k_gx,   cudaFuncAttributeMaxDynamicSharedMemorySize, GX_SMEM);
    cudaFuncSetAttribute(k_tail, cudaFuncAttributeMaxDynamicSharedMemorySize, TAIL_SMEM);

    dim3 g1(G3 / 64, (BB * TT) / 128), b1(16, 16);
    k_gx  <<<g1, b1, GX_SMEM>>>(x, w_ih, b_ih);
    k_gru <<<(BB / NBAT) * CL, G3>>>(hidden, w_hh, b_hh, out_hT);
    k_tail<<<(BB * TT) / PAIRS, 1024, TAIL_SMEM>>>(x, w_lat, b_lat, w_par, b_par, out_mean, out_std);
}